// round 2
// baseline (speedup 1.0000x reference)
#include <cuda_runtime.h>
#include <cuda_bf16.h>
#include <math.h>

#define N_NODES 50000
#define N_EDGES 800000
#define D 128
#define C 32
#define G 64
#define EPS 1e-5f
#define NUM_LAYERS 3

// ---------------- scratch (device globals; no allocation allowed) ----------
__device__ float g_bufA[N_NODES * D];
__device__ float g_bufB[N_NODES * D];
__device__ float g_S[N_NODES * D];
__device__ float g_pooled[G * D];
__device__ int   g_deg[N_NODES];
__device__ int   g_rowptr[N_NODES + 1];
__device__ int   g_cursor[N_NODES];
__device__ int   g_col[N_EDGES];
__device__ int   g_goff[G + 1];

// ---------------- CSR build ------------------------------------------------
__global__ void k_zero_deg() {
    int n = blockIdx.x * blockDim.x + threadIdx.x;
    if (n < N_NODES) g_deg[n] = 0;
}

__global__ void k_count_deg(const int* __restrict__ ei) {
    int e = blockIdx.x * blockDim.x + threadIdx.x;
    if (e < N_EDGES) atomicAdd(&g_deg[ei[N_EDGES + e]], 1);
}

// single-block exclusive scan of deg -> rowptr (+ cursor copy)
__global__ void k_scan() {
    __shared__ int s[1024];
    const int t = threadIdx.x;
    const int ITEMS = (N_NODES + 1023) / 1024;  // 49
    int base = t * ITEMS;
    int loc = 0;
    for (int i = 0; i < ITEMS; i++) {
        int idx = base + i;
        if (idx < N_NODES) loc += g_deg[idx];
    }
    s[t] = loc;
    __syncthreads();
    for (int off = 1; off < 1024; off <<= 1) {
        int v = 0;
        if (t >= off) v = s[t - off];
        __syncthreads();
        s[t] += v;
        __syncthreads();
    }
    int run = (t == 0) ? 0 : s[t - 1];
    for (int i = 0; i < ITEMS; i++) {
        int idx = base + i;
        if (idx < N_NODES) {
            g_rowptr[idx] = run;
            g_cursor[idx] = run;
            run += g_deg[idx];
        }
    }
    if (t == 1023) g_rowptr[N_NODES] = s[1023];
}

__global__ void k_fill_csr(const int* __restrict__ ei) {
    int e = blockIdx.x * blockDim.x + threadIdx.x;
    if (e < N_EDGES) {
        int dst = ei[N_EDGES + e];
        int pos = atomicAdd(&g_cursor[dst], 1);
        g_col[pos] = ei[e];
    }
}

// graph boundary offsets from sorted batch vector
__global__ void k_goff(const int* __restrict__ batch) {
    int n = blockIdx.x * blockDim.x + threadIdx.x;
    if (n >= N_NODES) return;
    int bn = batch[n];
    int bp = (n == 0) ? -1 : batch[n - 1];
    for (int g = bp + 1; g <= bn; g++) g_goff[g] = n;
    if (n == N_NODES - 1) {
        for (int g = bn + 1; g <= G; g++) g_goff[g] = N_NODES;
    }
}

// ---------------- neighbor scatter-sum of raw x (warp per node) ------------
__global__ void k_agg(const float* __restrict__ x, float* __restrict__ S) {
    int warp = (blockIdx.x * blockDim.x + threadIdx.x) >> 5;
    int lane = threadIdx.x & 31;
    if (warp >= N_NODES) return;
    int s0 = g_rowptr[warp], s1 = g_rowptr[warp + 1];
    float4 acc = make_float4(0.f, 0.f, 0.f, 0.f);
    for (int e = s0; e < s1; e++) {
        int src = g_col[e];
        float4 v = ((const float4*)(x + (size_t)src * D))[lane];
        acc.x += v.x; acc.y += v.y; acc.z += v.z; acc.w += v.w;
    }
    ((float4*)(S + (size_t)warp * D))[lane] = acc;
}

// ---------------- fused conv GEMM: out = relu(X@Ws + S@Wm + bs + deg*bm) ---
// BM=64 rows, BN=128 cols (=D), K=256 (X||S), BK=32, 128 threads, 8x8 microtile
#define BM 64
#define BK 32

__global__ void __launch_bounds__(128)
k_conv(const float* __restrict__ X, const float* __restrict__ S,
       const float* __restrict__ Ws, const float* __restrict__ Wm,
       const float* __restrict__ bs, const float* __restrict__ bm,
       float* __restrict__ out) {
    __shared__ float As[BK][BM + 1];  // +1 pad: conflict-free transposed stores
    __shared__ float Bs[BK][D];

    const int m0 = blockIdx.x * BM;
    const int tid = threadIdx.x;
    const int ct = tid & 15;   // 16 col-threads * 8 cols = 128
    const int rt = tid >> 4;   // 8 row-threads  * 8 rows = 64

    float acc[8][8];
#pragma unroll
    for (int i = 0; i < 8; i++)
#pragma unroll
        for (int j = 0; j < 8; j++) acc[i][j] = 0.f;

    for (int kc = 0; kc < 8; kc++) {  // 8 chunks of 32 over K=256
        const float* Asrc = (kc < 4) ? X : S;
        const float* Bsrc = (kc < 4) ? Ws : Wm;
        const int kbase = ((kc < 4) ? kc : kc - 4) * BK;

        // load A tile: 64 rows x 32 k, transposed into As[k][row]
#pragma unroll
        for (int i = 0; i < 4; i++) {
            int idx = tid + i * 128;       // 0..511 float4 slots
            int row = idx >> 3;            // 0..63
            int k4 = idx & 7;              // 0..7
            int grow = m0 + row;
            float4 v = make_float4(0.f, 0.f, 0.f, 0.f);
            if (grow < N_NODES)
                v = *(const float4*)(Asrc + (size_t)grow * D + kbase + k4 * 4);
            As[k4 * 4 + 0][row] = v.x;
            As[k4 * 4 + 1][row] = v.y;
            As[k4 * 4 + 2][row] = v.z;
            As[k4 * 4 + 3][row] = v.w;
        }
        // load B tile: 32 k x 128 cols, row-major
#pragma unroll
        for (int i = 0; i < 8; i++) {
            int idx = tid + i * 128;       // 0..1023 float4 slots
            int k = idx >> 5;
            int c4 = idx & 31;
            float4 v = *(const float4*)(Bsrc + (size_t)(kbase + k) * D + c4 * 4);
            *(float4*)&Bs[k][c4 * 4] = v;
        }
        __syncthreads();

#pragma unroll
        for (int k = 0; k < BK; k++) {
            float a[8], b[8];
#pragma unroll
            for (int i = 0; i < 8; i++) a[i] = As[k][rt * 8 + i];
            float4 b0 = *(const float4*)&Bs[k][ct * 8];
            float4 b1 = *(const float4*)&Bs[k][ct * 8 + 4];
            b[0] = b0.x; b[1] = b0.y; b[2] = b0.z; b[3] = b0.w;
            b[4] = b1.x; b[5] = b1.y; b[6] = b1.z; b[7] = b1.w;
#pragma unroll
            for (int i = 0; i < 8; i++)
#pragma unroll
                for (int j = 0; j < 8; j++) acc[i][j] += a[i] * b[j];
        }
        __syncthreads();
    }

    // epilogue: + b_self + deg*b_msg, relu
    const int c0 = ct * 8;
    float bsv[8], bmv[8];
#pragma unroll
    for (int j = 0; j < 8; j++) { bsv[j] = bs[c0 + j]; bmv[j] = bm[c0 + j]; }
#pragma unroll
    for (int i = 0; i < 8; i++) {
        int row = m0 + rt * 8 + i;
        if (row < N_NODES) {
            float degf = (float)(g_rowptr[row + 1] - g_rowptr[row]);
            float4 o0, o1;
            o0.x = fmaxf(acc[i][0] + bsv[0] + degf * bmv[0], 0.f);
            o0.y = fmaxf(acc[i][1] + bsv[1] + degf * bmv[1], 0.f);
            o0.z = fmaxf(acc[i][2] + bsv[2] + degf * bmv[2], 0.f);
            o0.w = fmaxf(acc[i][3] + bsv[3] + degf * bmv[3], 0.f);
            o1.x = fmaxf(acc[i][4] + bsv[4] + degf * bmv[4], 0.f);
            o1.y = fmaxf(acc[i][5] + bsv[5] + degf * bmv[5], 0.f);
            o1.z = fmaxf(acc[i][6] + bsv[6] + degf * bmv[6], 0.f);
            o1.w = fmaxf(acc[i][7] + bsv[7] + degf * bmv[7], 0.f);
            *(float4*)(out + (size_t)row * D + c0) = o0;
            *(float4*)(out + (size_t)row * D + c0 + 4) = o1;
        }
    }
}

// ---------------- LayerNorm (warp per node, in-place) ----------------------
__global__ void k_ln(float* __restrict__ x, const float* __restrict__ gw,
                     const float* __restrict__ gb) {
    int warp = (blockIdx.x * blockDim.x + threadIdx.x) >> 5;
    int lane = threadIdx.x & 31;
    if (warp >= N_NODES) return;
    float4 v = ((const float4*)(x + (size_t)warp * D))[lane];
    float s = v.x + v.y + v.z + v.w;
#pragma unroll
    for (int off = 16; off > 0; off >>= 1) s += __shfl_xor_sync(0xffffffffu, s, off);
    float mean = s * (1.0f / D);
    float dx = v.x - mean, dy = v.y - mean, dz = v.z - mean, dw = v.w - mean;
    float sq = dx * dx + dy * dy + dz * dz + dw * dw;
#pragma unroll
    for (int off = 16; off > 0; off >>= 1) sq += __shfl_xor_sync(0xffffffffu, sq, off);
    float rs = rsqrtf(sq * (1.0f / D) + EPS);
    float4 g4 = ((const float4*)gw)[lane];
    float4 b4 = ((const float4*)gb)[lane];
    float4 o;
    o.x = g4.x * dx * rs + b4.x;
    o.y = g4.y * dy * rs + b4.y;
    o.z = g4.z * dz * rs + b4.z;
    o.w = g4.w * dw * rs + b4.w;
    ((float4*)(x + (size_t)warp * D))[lane] = o;
}

// ---------------- global mean pool (block per graph) -----------------------
__global__ void k_pool(const float* __restrict__ x) {
    int g = blockIdx.x, t = threadIdx.x;  // 128 threads
    int s = g_goff[g], e = g_goff[g + 1];
    float acc = 0.f;
    for (int n = s; n < e; n++) acc += x[(size_t)n * D + t];
    float cnt = (float)(e - s);
    if (cnt < 1.f) cnt = 1.f;
    g_pooled[g * D + t] = acc / cnt;
}

// ---------------- head: Linear(D,D) -> Linear(D,C) -> log_softmax ----------
__global__ void k_head(const float* __restrict__ W1, const float* __restrict__ b1,
                       const float* __restrict__ W2, const float* __restrict__ b2,
                       float* __restrict__ out) {
    __shared__ float p[D];
    __shared__ float h[D];
    int g = blockIdx.x, t = threadIdx.x;  // 128 threads
    p[t] = g_pooled[g * D + t];
    __syncthreads();
    float acc = b1[t];
#pragma unroll 8
    for (int k = 0; k < D; k++) acc += p[k] * W1[k * D + t];
    h[t] = acc;
    __syncthreads();
    if (t < C) {
        float a = b2[t];
#pragma unroll 8
        for (int k = 0; k < D; k++) a += h[k] * W2[k * C + t];
        float v = a;
        float mx = v;
#pragma unroll
        for (int off = 16; off > 0; off >>= 1)
            mx = fmaxf(mx, __shfl_xor_sync(0xffffffffu, mx, off));
        float ex = expf(v - mx);
        float sum = ex;
#pragma unroll
        for (int off = 16; off > 0; off >>= 1)
            sum += __shfl_xor_sync(0xffffffffu, sum, off);
        out[g * C + t] = v - mx - logf(sum);
    }
}

// ---------------- launch ---------------------------------------------------
extern "C" void kernel_launch(void* const* d_in, const int* in_sizes, int n_in,
                              void* d_out, int out_size) {
    const float* x      = (const float*)d_in[0];
    const float* W_self = (const float*)d_in[1];
    const float* b_self = (const float*)d_in[2];
    const float* W_msg  = (const float*)d_in[3];
    const float* b_msg  = (const float*)d_in[4];
    const float* ln_g   = (const float*)d_in[5];
    const float* ln_b   = (const float*)d_in[6];
    const float* W1     = (const float*)d_in[7];
    const float* b1     = (const float*)d_in[8];
    const float* W2     = (const float*)d_in[9];
    const float* b2     = (const float*)d_in[10];
    const int* ei       = (const int*)d_in[11];
    const int* batch    = (const int*)d_in[12];
    float* out          = (float*)d_out;

    float *bufA, *bufB, *S;
    cudaGetSymbolAddress((void**)&bufA, g_bufA);
    cudaGetSymbolAddress((void**)&bufB, g_bufB);
    cudaGetSymbolAddress((void**)&S, g_S);

    // CSR build
    k_zero_deg<<<(N_NODES + 255) / 256, 256>>>();
    k_count_deg<<<(N_EDGES + 255) / 256, 256>>>(ei);
    k_scan<<<1, 1024>>>();
    k_fill_csr<<<(N_EDGES + 255) / 256, 256>>>(ei);
    k_goff<<<(N_NODES + 255) / 256, 256>>>(batch);

    const int aggBlocks = (N_NODES * 32 + 255) / 256;
    const int convBlocks = (N_NODES + BM - 1) / BM;
    const int lnBlocks = (N_NODES * 32 + 255) / 256;

    const float* xin = x;
    float* xout = bufA;
    for (int l = 0; l < NUM_LAYERS; l++) {
        k_agg<<<aggBlocks, 256>>>(xin, S);
        k_conv<<<convBlocks, 128>>>(xin, S,
                                    W_self + (size_t)l * D * D,
                                    W_msg + (size_t)l * D * D,
                                    b_self + (size_t)l * D,
                                    b_msg + (size_t)l * D,
                                    xout);
        if (l < NUM_LAYERS - 1)
            k_ln<<<lnBlocks, 256>>>(xout, ln_g + (size_t)l * D, ln_b + (size_t)l * D);
        xin = xout;
        xout = (xout == bufA) ? bufB : bufA;
    }

    k_pool<<<G, D>>>(xin);
    k_head<<<G, D>>>(W1, b1, W2, b2, out);
}

// round 3
// speedup vs baseline: 1.4745x; 1.4745x over previous
#include <cuda_runtime.h>
#include <cuda_bf16.h>
#include <math.h>

#define N_NODES 50000
#define N_EDGES 800000
#define D 128
#define C 32
#define G 64
#define EPS 1e-5f
#define NUM_LAYERS 3

// ---------------- scratch (device globals; no allocation allowed) ----------
__device__ float g_bufA[N_NODES * D];
__device__ float g_bufB[N_NODES * D];
__device__ float g_S[N_NODES * D];
__device__ float g_pooled[G * D];
__device__ int   g_deg[N_NODES];
__device__ int   g_rowptr[N_NODES + 1];
__device__ int   g_cursor[N_NODES];
__device__ int   g_col[N_EDGES];
__device__ int   g_goff[G + 1];

// ---------------- CSR build ------------------------------------------------
__global__ void k_zero_deg() {
    int n = blockIdx.x * blockDim.x + threadIdx.x;
    if (n < N_NODES) g_deg[n] = 0;
}

__global__ void k_count_deg(const int* __restrict__ ei) {
    int e = blockIdx.x * blockDim.x + threadIdx.x;
    if (e < N_EDGES) atomicAdd(&g_deg[ei[N_EDGES + e]], 1);
}

__global__ void k_scan() {
    __shared__ int s[1024];
    const int t = threadIdx.x;
    const int ITEMS = (N_NODES + 1023) / 1024;  // 49
    int base = t * ITEMS;
    int loc = 0;
    for (int i = 0; i < ITEMS; i++) {
        int idx = base + i;
        if (idx < N_NODES) loc += g_deg[idx];
    }
    s[t] = loc;
    __syncthreads();
    for (int off = 1; off < 1024; off <<= 1) {
        int v = 0;
        if (t >= off) v = s[t - off];
        __syncthreads();
        s[t] += v;
        __syncthreads();
    }
    int run = (t == 0) ? 0 : s[t - 1];
    for (int i = 0; i < ITEMS; i++) {
        int idx = base + i;
        if (idx < N_NODES) {
            g_rowptr[idx] = run;
            g_cursor[idx] = run;
            run += g_deg[idx];
        }
    }
    if (t == 1023) g_rowptr[N_NODES] = s[1023];
}

__global__ void k_fill_csr(const int* __restrict__ ei) {
    int e = blockIdx.x * blockDim.x + threadIdx.x;
    if (e < N_EDGES) {
        int dst = ei[N_EDGES + e];
        int pos = atomicAdd(&g_cursor[dst], 1);
        g_col[pos] = ei[e];
    }
}

__global__ void k_goff(const int* __restrict__ batch) {
    int n = blockIdx.x * blockDim.x + threadIdx.x;
    if (n >= N_NODES) return;
    int bn = batch[n];
    int bp = (n == 0) ? -1 : batch[n - 1];
    for (int g = bp + 1; g <= bn; g++) g_goff[g] = n;
    if (n == N_NODES - 1) {
        for (int g = bn + 1; g <= G; g++) g_goff[g] = N_NODES;
    }
}

// ---------------- neighbor scatter-sum of raw x (warp per node) ------------
__global__ void k_agg(const float* __restrict__ x, float* __restrict__ S) {
    int warp = (blockIdx.x * blockDim.x + threadIdx.x) >> 5;
    int lane = threadIdx.x & 31;
    if (warp >= N_NODES) return;
    int s0 = g_rowptr[warp], s1 = g_rowptr[warp + 1];
    float4 acc = make_float4(0.f, 0.f, 0.f, 0.f);
    for (int e = s0; e < s1; e++) {
        int src = g_col[e];
        float4 v = ((const float4*)(x + (size_t)src * D))[lane];
        acc.x += v.x; acc.y += v.y; acc.z += v.z; acc.w += v.w;
    }
    ((float4*)(S + (size_t)warp * D))[lane] = acc;
}

// ---------------- TF32 tensor-core conv GEMM -------------------------------
// out = relu(X@Ws + S@Wm + bs + deg*bm), optionally LayerNorm fused.
// BM=128 rows, BN=128 (=D), K=256 (X||S) in BK=32 chunks.
// 256 threads = 8 warps, warp grid 4(M) x 2(N), warp tile 32x64,
// mma.sync m16n8k8 tf32: 2 m-tiles x 8 n-tiles per warp.

__device__ __forceinline__ unsigned f2tf(float f) {
    unsigned u;
    asm("cvt.rna.tf32.f32 %0, %1;" : "=r"(u) : "f"(f));
    return u;
}

__device__ __forceinline__ void mma_tf32(float* d, const unsigned* a, const unsigned* b) {
    asm volatile(
        "mma.sync.aligned.m16n8k8.row.col.f32.tf32.tf32.f32 "
        "{%0,%1,%2,%3}, {%4,%5,%6,%7}, {%8,%9}, {%0,%1,%2,%3};"
        : "+f"(d[0]), "+f"(d[1]), "+f"(d[2]), "+f"(d[3])
        : "r"(a[0]), "r"(a[1]), "r"(a[2]), "r"(a[3]), "r"(b[0]), "r"(b[1]));
}

#define AS_STRIDE 36   // 36 mod 32 = 4 -> frag loads bank = 4*g + tig (unique)
#define BS_STRIDE 136  // 136 mod 32 = 8 -> frag loads bank = 8*tig + g (unique)

__global__ void __launch_bounds__(256, 2)
k_conv(const float* __restrict__ X, const float* __restrict__ S,
       const float* __restrict__ Ws, const float* __restrict__ Wm,
       const float* __restrict__ bs, const float* __restrict__ bm,
       const float* __restrict__ lng, const float* __restrict__ lnb,
       int do_ln, float* __restrict__ out) {
    __shared__ unsigned As_u[128 * AS_STRIDE];
    __shared__ unsigned Bs_u[32 * BS_STRIDE];
    __shared__ float red_s[2][128];
    __shared__ float red_q[2][128];

    const int tid = threadIdx.x;
    const int m0 = blockIdx.x * 128;
    const int warpId = tid >> 5;
    const int warpM = warpId >> 1;        // 0..3
    const int warpN = warpId & 1;         // 0..1
    const int lane = tid & 31;
    const int g = lane >> 2;              // 0..7
    const int tig = lane & 3;             // 0..3

    float acc[2][8][4];
#pragma unroll
    for (int mt = 0; mt < 2; mt++)
#pragma unroll
        for (int nt = 0; nt < 8; nt++)
#pragma unroll
            for (int r = 0; r < 4; r++) acc[mt][nt][r] = 0.f;

    for (int kc = 0; kc < 8; kc++) {
        const float* Asrc = (kc < 4) ? X : S;
        const float* Bsrc = (kc < 4) ? Ws : Wm;
        const int kbase = (kc & 3) * 32;

        // stage A: 128 rows x 32 k (converted to tf32)
#pragma unroll
        for (int i = 0; i < 4; i++) {
            int idx = tid + i * 256;       // 0..1023 float4 slots
            int row = idx >> 3;
            int k4 = idx & 7;
            int grow = m0 + row;
            float4 v = make_float4(0.f, 0.f, 0.f, 0.f);
            if (grow < N_NODES)
                v = *(const float4*)(Asrc + (size_t)grow * D + kbase + k4 * 4);
            uint4 u;
            u.x = f2tf(v.x); u.y = f2tf(v.y); u.z = f2tf(v.z); u.w = f2tf(v.w);
            *(uint4*)&As_u[row * AS_STRIDE + k4 * 4] = u;
        }
        // stage B: 32 k x 128 n
#pragma unroll
        for (int i = 0; i < 4; i++) {
            int idx = tid + i * 256;       // 0..1023 float4 slots
            int k = idx >> 5;
            int n4 = idx & 31;
            float4 v = *(const float4*)(Bsrc + (size_t)(kbase + k) * D + n4 * 4);
            uint4 u;
            u.x = f2tf(v.x); u.y = f2tf(v.y); u.z = f2tf(v.z); u.w = f2tf(v.w);
            *(uint4*)&Bs_u[k * BS_STRIDE + n4 * 4] = u;
        }
        __syncthreads();

#pragma unroll
        for (int ks = 0; ks < 4; ks++) {
            const int kof = ks * 8;
            unsigned a[2][4], b[8][2];
#pragma unroll
            for (int mt = 0; mt < 2; mt++) {
                int r0 = warpM * 32 + mt * 16 + g;
                a[mt][0] = As_u[r0 * AS_STRIDE + kof + tig];
                a[mt][1] = As_u[(r0 + 8) * AS_STRIDE + kof + tig];
                a[mt][2] = As_u[r0 * AS_STRIDE + kof + tig + 4];
                a[mt][3] = As_u[(r0 + 8) * AS_STRIDE + kof + tig + 4];
            }
#pragma unroll
            for (int nt = 0; nt < 8; nt++) {
                int c = warpN * 64 + nt * 8 + g;
                b[nt][0] = Bs_u[(kof + tig) * BS_STRIDE + c];
                b[nt][1] = Bs_u[(kof + tig + 4) * BS_STRIDE + c];
            }
#pragma unroll
            for (int mt = 0; mt < 2; mt++)
#pragma unroll
                for (int nt = 0; nt < 8; nt++)
                    mma_tf32(acc[mt][nt], a[mt], b[nt]);
        }
        __syncthreads();
    }

    // ---- epilogue: bias + deg*bm, relu, optional fused LayerNorm ----
    float degf[2][2];
    float s[2][2], q[2][2];
#pragma unroll
    for (int mt = 0; mt < 2; mt++)
#pragma unroll
        for (int h = 0; h < 2; h++) {
            int row = m0 + warpM * 32 + mt * 16 + h * 8 + g;
            degf[mt][h] = (row < N_NODES)
                ? (float)(g_rowptr[row + 1] - g_rowptr[row]) : 0.f;
            s[mt][h] = 0.f; q[mt][h] = 0.f;
        }

#pragma unroll
    for (int mt = 0; mt < 2; mt++)
#pragma unroll
        for (int nt = 0; nt < 8; nt++) {
            int c0 = warpN * 64 + nt * 8 + tig * 2;
            float bs0 = bs[c0], bs1 = bs[c0 + 1];
            float bm0 = bm[c0], bm1 = bm[c0 + 1];
#pragma unroll
            for (int h = 0; h < 2; h++) {
                float t0 = fmaxf(acc[mt][nt][h * 2 + 0] + bs0 + degf[mt][h] * bm0, 0.f);
                float t1 = fmaxf(acc[mt][nt][h * 2 + 1] + bs1 + degf[mt][h] * bm1, 0.f);
                acc[mt][nt][h * 2 + 0] = t0;
                acc[mt][nt][h * 2 + 1] = t1;
                s[mt][h] += t0 + t1;
                q[mt][h] += t0 * t0 + t1 * t1;
            }
        }

    if (do_ln) {
#pragma unroll
        for (int mt = 0; mt < 2; mt++)
#pragma unroll
            for (int h = 0; h < 2; h++) {
                float ss = s[mt][h], qq = q[mt][h];
                ss += __shfl_xor_sync(0xffffffffu, ss, 1);
                ss += __shfl_xor_sync(0xffffffffu, ss, 2);
                qq += __shfl_xor_sync(0xffffffffu, qq, 1);
                qq += __shfl_xor_sync(0xffffffffu, qq, 2);
                if (tig == 0) {
                    int rb = warpM * 32 + mt * 16 + h * 8 + g;
                    red_s[warpN][rb] = ss;
                    red_q[warpN][rb] = qq;
                }
            }
        __syncthreads();
#pragma unroll
        for (int mt = 0; mt < 2; mt++)
#pragma unroll
            for (int h = 0; h < 2; h++) {
                int rb = warpM * 32 + mt * 16 + h * 8 + g;
                int row = m0 + rb;
                if (row >= N_NODES) continue;
                float SS = red_s[0][rb] + red_s[1][rb];
                float QQ = red_q[0][rb] + red_q[1][rb];
                float mean = SS * (1.0f / D);
                float var = QQ * (1.0f / D) - mean * mean;
                float rstd = rsqrtf(var + EPS);
#pragma unroll
                for (int nt = 0; nt < 8; nt++) {
                    int c0 = warpN * 64 + nt * 8 + tig * 2;
                    float2 o;
                    o.x = lng[c0] * (acc[mt][nt][h * 2 + 0] - mean) * rstd + lnb[c0];
                    o.y = lng[c0 + 1] * (acc[mt][nt][h * 2 + 1] - mean) * rstd + lnb[c0 + 1];
                    *(float2*)(out + (size_t)row * D + c0) = o;
                }
            }
    } else {
#pragma unroll
        for (int mt = 0; mt < 2; mt++)
#pragma unroll
            for (int h = 0; h < 2; h++) {
                int row = m0 + warpM * 32 + mt * 16 + h * 8 + g;
                if (row >= N_NODES) continue;
#pragma unroll
                for (int nt = 0; nt < 8; nt++) {
                    int c0 = warpN * 64 + nt * 8 + tig * 2;
                    float2 o;
                    o.x = acc[mt][nt][h * 2 + 0];
                    o.y = acc[mt][nt][h * 2 + 1];
                    *(float2*)(out + (size_t)row * D + c0) = o;
                }
            }
    }
}

// ---------------- global mean pool (block per graph) -----------------------
__global__ void k_pool(const float* __restrict__ x) {
    int g = blockIdx.x, t = threadIdx.x;  // 128 threads
    int s = g_goff[g], e = g_goff[g + 1];
    float acc = 0.f;
    for (int n = s; n < e; n++) acc += x[(size_t)n * D + t];
    float cnt = (float)(e - s);
    if (cnt < 1.f) cnt = 1.f;
    g_pooled[g * D + t] = acc / cnt;
}

// ---------------- head: Linear(D,D) -> Linear(D,C) -> log_softmax ----------
__global__ void k_head(const float* __restrict__ W1, const float* __restrict__ b1,
                       const float* __restrict__ W2, const float* __restrict__ b2,
                       float* __restrict__ out) {
    __shared__ float p[D];
    __shared__ float h[D];
    int g = blockIdx.x, t = threadIdx.x;  // 128 threads
    p[t] = g_pooled[g * D + t];
    __syncthreads();
    float acc = b1[t];
#pragma unroll 8
    for (int k = 0; k < D; k++) acc += p[k] * W1[k * D + t];
    h[t] = acc;
    __syncthreads();
    if (t < C) {
        float a = b2[t];
#pragma unroll 8
        for (int k = 0; k < D; k++) a += h[k] * W2[k * C + t];
        float v = a;
        float mx = v;
#pragma unroll
        for (int off = 16; off > 0; off >>= 1)
            mx = fmaxf(mx, __shfl_xor_sync(0xffffffffu, mx, off));
        float ex = expf(v - mx);
        float sum = ex;
#pragma unroll
        for (int off = 16; off > 0; off >>= 1)
            sum += __shfl_xor_sync(0xffffffffu, sum, off);
        out[g * C + t] = v - mx - logf(sum);
    }
}

// ---------------- launch ---------------------------------------------------
extern "C" void kernel_launch(void* const* d_in, const int* in_sizes, int n_in,
                              void* d_out, int out_size) {
    const float* x      = (const float*)d_in[0];
    const float* W_self = (const float*)d_in[1];
    const float* b_self = (const float*)d_in[2];
    const float* W_msg  = (const float*)d_in[3];
    const float* b_msg  = (const float*)d_in[4];
    const float* ln_g   = (const float*)d_in[5];
    const float* ln_b   = (const float*)d_in[6];
    const float* W1     = (const float*)d_in[7];
    const float* b1     = (const float*)d_in[8];
    const float* W2     = (const float*)d_in[9];
    const float* b2     = (const float*)d_in[10];
    const int* ei       = (const int*)d_in[11];
    const int* batch    = (const int*)d_in[12];
    float* out          = (float*)d_out;

    float *bufA, *bufB, *S;
    cudaGetSymbolAddress((void**)&bufA, g_bufA);
    cudaGetSymbolAddress((void**)&bufB, g_bufB);
    cudaGetSymbolAddress((void**)&S, g_S);

    // CSR build
    k_zero_deg<<<(N_NODES + 255) / 256, 256>>>();
    k_count_deg<<<(N_EDGES + 255) / 256, 256>>>(ei);
    k_scan<<<1, 1024>>>();
    k_fill_csr<<<(N_EDGES + 255) / 256, 256>>>(ei);
    k_goff<<<(N_NODES + 255) / 256, 256>>>(batch);

    const int aggBlocks = (N_NODES * 32 + 255) / 256;
    const int convBlocks = (N_NODES + 127) / 128;

    const float* xin = x;
    float* xout = bufA;
    for (int l = 0; l < NUM_LAYERS; l++) {
        int do_ln = (l < NUM_LAYERS - 1) ? 1 : 0;
        const float* lg = ln_g + (size_t)(do_ln ? l : 0) * D;
        const float* lb = ln_b + (size_t)(do_ln ? l : 0) * D;
        k_agg<<<aggBlocks, 256>>>(xin, S);
        k_conv<<<convBlocks, 256>>>(xin, S,
                                    W_self + (size_t)l * D * D,
                                    W_msg + (size_t)l * D * D,
                                    b_self + (size_t)l * D,
                                    b_msg + (size_t)l * D,
                                    lg, lb, do_ln, xout);
        xin = xout;
        xout = (xout == bufA) ? bufB : bufA;
    }

    k_pool<<<G, D>>>(xin);
    k_head<<<G, D>>>(W1, b1, W2, b2, out);
}